// round 16
// baseline (speedup 1.0000x reference)
#include <cuda_runtime.h>
#include <cuda_fp16.h>
#include <cstdint>

#define S_LEN 2048
#define BATCH 2
#define HID   1024
#define NHEAD 16
#define HDIM  64
#define FFN_D 4096
#define MTOT  (BATCH * S_LEN)   // 4096
#define MEG   (1u << 20)

// ---------------- scratch ----------------
static __device__ __half g_Qh[(size_t)BATCH * NHEAD * S_LEN * HDIM];   // fp16, pre-scaled log2e/8
static __device__ __half g_Kh[(size_t)BATCH * NHEAD * S_LEN * HDIM];
static __device__ __half g_Vh[(size_t)BATCH * NHEAD * S_LEN * HDIM];
static __device__ __half g_ctxh[(size_t)MTOT * HID];
static __device__ float  g_att[(size_t)MTOT * HID];
static __device__ __half g_atth[(size_t)MTOT * HID];
static __device__ __half g_ffnh[(size_t)MTOT * FFN_D];
static __device__ __half g_w16[24 * MEG];
static __device__ __half g_maskh[(size_t)BATCH * S_LEN * S_LEN];       // additive fp16 mask, permuted
static __device__ int g_mflag;

// fp16 pool offsets (elements)
#define O_SQ 0
#define O_SK (4 * MEG)
#define O_SV (8 * MEG)
#define O_WQ (12 * MEG)
#define O_WK (13 * MEG)
#define O_WV (14 * MEG)
#define O_WO (15 * MEG)
#define O_W1 (16 * MEG)
#define O_W2 (20 * MEG)

__device__ __forceinline__ uint32_t smem_u32(const void* p) {
    uint32_t a;
    asm("{ .reg .u64 t; cvta.to.shared.u64 t, %1; cvt.u32.u64 %0, t; }" : "=r"(a) : "l"(p));
    return a;
}
__device__ __forceinline__ void ldsm4(uint32_t* r, uint32_t a) {
    asm volatile("ldmatrix.sync.aligned.m8n8.x4.shared.b16 {%0,%1,%2,%3}, [%4];"
        : "=r"(r[0]), "=r"(r[1]), "=r"(r[2]), "=r"(r[3]) : "r"(a));
}
__device__ __forceinline__ void ldsm4t(uint32_t* r, uint32_t a) {
    asm volatile("ldmatrix.sync.aligned.m8n8.x4.trans.shared.b16 {%0,%1,%2,%3}, [%4];"
        : "=r"(r[0]), "=r"(r[1]), "=r"(r[2]), "=r"(r[3]) : "r"(a));
}
__device__ __forceinline__ void ldsm2t(uint32_t* r, uint32_t a) {
    asm volatile("ldmatrix.sync.aligned.m8n8.x2.trans.shared.b16 {%0,%1}, [%2];"
        : "=r"(r[0]), "=r"(r[1]) : "r"(a));
}
__device__ __forceinline__ void mma16816(float* c, const uint32_t* a, const uint32_t* b) {
    asm volatile("mma.sync.aligned.m16n8k16.row.col.f32.f16.f16.f32 "
        "{%0,%1,%2,%3}, {%4,%5,%6,%7}, {%8,%9}, {%0,%1,%2,%3};"
        : "+f"(c[0]), "+f"(c[1]), "+f"(c[2]), "+f"(c[3])
        : "r"(a[0]), "r"(a[1]), "r"(a[2]), "r"(a[3]), "r"(b[0]), "r"(b[1]));
}
__device__ __forceinline__ void cp16(uint32_t d, const void* g) {
    asm volatile("cp.async.cg.shared.global [%0], [%1], 16;" :: "r"(d), "l"(g) : "memory");
}
template <int N> __device__ __forceinline__ void cp_wait() {
    asm volatile("cp.async.wait_group %0;" :: "n"(N) : "memory");
}
__device__ __forceinline__ uint32_t packh2(float a, float b) {
    __half2 h = __floats2half2_rn(a, b);
    return *(uint32_t*)&h;
}

// half2 2^t (same bit-for-bit result path as R13/R14; lacc side-effect removed)
__device__ __forceinline__ uint32_t hexp2(__half2 t) {
    const __half2 mag = __floats2half2_rn(1536.f, 1536.f);
    const __half2 lo  = __floats2half2_rn(-14.f, -14.f);
    const __half2 c4 = __floats2half2_rn(0.0096180f, 0.0096180f);
    const __half2 c3 = __floats2half2_rn(0.0555041f, 0.0555041f);
    const __half2 c2 = __floats2half2_rn(0.2402265f, 0.2402265f);
    const __half2 c1 = __floats2half2_rn(0.6931472f, 0.6931472f);
    const __half2 c0 = __floats2half2_rn(1.0f, 1.0f);
    t = __hmax2(t, lo);
    __half2 z = __hadd2(t, mag);
    __half2 n = __hsub2(z, mag);
    __half2 f = __hsub2(t, n);
    __half2 p = __hfma2(c4, f, c3);
    p = __hfma2(p, f, c2);
    p = __hfma2(p, f, c1);
    p = __hfma2(p, f, c0);
    uint32_t zb = *(uint32_t*)&z;
    uint32_t sc = ((zb + 0x000F000Fu) & 0x003F003Fu) << 10;
    __half2 r = __hmul2(p, *(__half2*)&sc);
    return *(uint32_t*)&r;
}

// ---------------- mask dtype detection ----------------
__global__ void detect_mask_kernel(const unsigned int* __restrict__ m)
{
    int tid = threadIdx.x;
    int okI = 1, okF = 1;
#pragma unroll
    for (int i = 0; i < 4; i++) {
        unsigned v = m[tid * 4 + i];
        if (v > 1u) okI = 0;
        if (v != 0u && v != 0x3F800000u) okF = 0;
    }
    okI = __syncthreads_and(okI);
    okF = __syncthreads_and(okF);
    if (tid == 0) g_mflag = okI ? 1 : (okF ? 2 : 0);
}

// additive fp16 mask, permuted (validated R14)
__global__ __launch_bounds__(256) void mask_convert_h(const void* __restrict__ mask)
{
    size_t o8 = ((size_t)blockIdx.x * 256 + threadIdx.x) * 8;
    size_t rowS = o8 >> 11;
    int within = (int)(o8 & 2047);
    int kt = within >> 6;
    int p0 = within & 63;
    int tg = p0 >> 4;
    int j0 = (p0 & 15) >> 1;
    int f = g_mflag;
    const size_t ibase = rowS * 2048 + (size_t)kt * 64 + tg * 2;
    unsigned short hh[8];
#pragma unroll
    for (int e = 0; e < 8; e++) {
        int j = j0 + (e >> 1), v = e & 1;
        size_t idx = ibase + j * 8 + v;
        bool msk;
        if (f == 1)      msk = ((const int*)mask)[idx] != 0;
        else if (f == 2) msk = ((const float*)mask)[idx] != 0.f;
        else             msk = ((const unsigned char*)mask)[idx] != 0;
        hh[e] = msk ? (unsigned short)0xFC00 : (unsigned short)0x0000;
    }
    uint4 u;
    u.x = (uint32_t)hh[0] | ((uint32_t)hh[1] << 16);
    u.y = (uint32_t)hh[2] | ((uint32_t)hh[3] << 16);
    u.z = (uint32_t)hh[4] | ((uint32_t)hh[5] << 16);
    u.w = (uint32_t)hh[6] | ((uint32_t)hh[7] << 16);
    *(uint4*)&g_maskh[o8] = u;
}

// ---------------- fused fp32 -> fp16 pre-convert (block-offset for split launch) --
__global__ __launch_bounds__(256) void f2h_all(
    const float* __restrict__ sq, const float* __restrict__ sk, const float* __restrict__ sv,
    const float* __restrict__ wq, const float* __restrict__ wk, const float* __restrict__ wv,
    const float* __restrict__ wo, const float* __restrict__ w1, const float* __restrict__ w2,
    int bk0)
{
    int bk = blockIdx.x + bk0;
    const float* src;
    int base;
    if (bk < 6144) {
        if (bk < 2048)      { src = sq; base = 0; }
        else if (bk < 4096) { src = sk; base = 2048; }
        else                { src = sv; base = 4096; }
    } else if (bk < 8192) {
        if (bk < 6656)      { src = wq; base = 6144; }
        else if (bk < 7168) { src = wk; base = 6656; }
        else if (bk < 7680) { src = wv; base = 7168; }
        else                { src = wo; base = 7680; }
    } else if (bk < 10240)  { src = w1; base = 8192; }
    else                    { src = w2; base = 10240; }

    size_t l = (size_t)(bk - base) * 2048 + threadIdx.x * 8;
    size_t g = (size_t)bk * 2048 + threadIdx.x * 8;
    float4 f0 = *(const float4*)(src + l);
    float4 f1 = *(const float4*)(src + l + 4);
    uint4 u;
    u.x = packh2(f0.x, f0.y);
    u.y = packh2(f0.z, f0.w);
    u.z = packh2(f1.x, f1.y);
    u.w = packh2(f1.z, f1.w);
    *(uint4*)&g_w16[g] = u;
}

// ---------------- fp16 GEMM: single-sync 3-stage pipeline (R14, passing) --------
#define GK_STAGE 32768
#define GEMM_SMEM3 (3 * GK_STAGE)

__device__ __forceinline__ void gemm_issue(uint32_t sb, int st,
    const __half* Ap, const __half* Wp, int K, int k0, int tid)
{
#pragma unroll
    for (int i = 0; i < 4; i++) {
        int idx = i * 256 + tid, r = idx >> 3, c = idx & 7;
        int phys = c ^ (r & 7);
        uint32_t da = sb + st * GK_STAGE + r * 128 + phys * 16;
        cp16(da, Ap + (size_t)r * K + k0 + c * 8);
        cp16(da + 16384, Wp + (size_t)r * K + k0 + c * 8);
    }
    asm volatile("cp.async.commit_group;" ::: "memory");
}

__device__ __forceinline__ void gemm_stage(uint32_t sb, int st,
    int wm, int wn, int lt, int lr, float acc[2][8][4])
{
    uint32_t base = sb + st * GK_STAGE;
#pragma unroll
    for (int kc = 0; kc < 4; kc++) {
        uint32_t aA[2][4];
#pragma unroll
        for (int mt = 0; mt < 2; mt++) {
            int row = wm * 32 + mt * 16 + (lt & 1) * 8 + lr;
            int phys = (2 * kc + (lt >> 1)) ^ (row & 7);
            ldsm4(aA[mt], base + row * 128 + phys * 16);
        }
#pragma unroll
        for (int p = 0; p < 4; p++) {
            int rowb = wn * 64 + p * 16 + (lt >> 1) * 8 + lr;
            int physb = (2 * kc + (lt & 1)) ^ (rowb & 7);
            uint32_t bk4[4];
            ldsm4(bk4, base + 16384 + rowb * 128 + physb * 16);
#pragma unroll
            for (int mt = 0; mt < 2; mt++) {
                mma16816(acc[mt][2 * p],     aA[mt], bk4);
                mma16816(acc[mt][2 * p + 1], aA[mt], bk4 + 2);
            }
        }
    }
}

__device__ __forceinline__ void gemm_body(
    const __half* __restrict__ A, const __half* __restrict__ W,
    const float* __restrict__ bias, float* __restrict__ Cf, __half* __restrict__ Ch,
    const float* __restrict__ Res, int N, int K, int mode)
{
    extern __shared__ __align__(1024) char smb[];
    const uint32_t sb = smem_u32(smb);
    const int tid = threadIdx.x;
    const int lane = tid & 31;
    const int wid = tid >> 5;
    const int wm = wid & 3, wn = wid >> 2;
    const int lt = lane >> 3, lr = lane & 7;
    const int gID = lane >> 2, tg = lane & 3;
    const int bm = blockIdx.y, bn = blockIdx.x;

    const __half* Ap = A + (size_t)bm * 128 * K;
    const __half* Wp = W + (size_t)bn * 128 * K;

    float acc[2][8][4];
#pragma unroll
    for (int mt = 0; mt < 2; mt++)
#pragma unroll
        for (int p = 0; p < 8; p++)
#pragma unroll
            for (int e = 0; e < 4; e++) acc[mt][p][e] = 0.f;

    const int nk = K >> 6;
    gemm_issue(sb, 0, Ap, Wp, K, 0, tid);
    gemm_issue(sb, 1, Ap, Wp, K, 64, tid);

#pragma unroll 1
    for (int t = 0; t < nk; t++) {
        if (t + 1 < nk) cp_wait<1>();
        else cp_wait<0>();
        __syncthreads();
        if (t + 2 < nk) gemm_issue(sb, (t + 2) % 3, Ap, Wp, K, (t + 2) * 64, tid);
        gemm_stage(sb, t % 3, wm, wn, lt, lr, acc);
    }

#pragma unroll
    for (int mt = 0; mt < 2; mt++) {
#pragma unroll
        for (int hh = 0; hh < 2; hh++) {
            int m = bm * 128 + wm * 32 + mt * 16 + gID + hh * 8;
#pragma unroll
            for (int p = 0; p < 8; p++) {
                int n = bn * 128 + wn * 64 + p * 8 + tg * 2;
                float v0 = acc[mt][p][2 * hh]     + bias[n];
                float v1 = acc[mt][p][2 * hh + 1] + bias[n + 1];
                if (mode == 0 || mode == 4) {
                    if (mode == 4) { v0 *= 0.18033688f; v1 *= 0.18033688f; }  // (1/8)*log2(e)
                    int b_ = m >> 11, s_ = m & (S_LEN - 1), h_ = n >> 6, d_ = n & 63;
                    *(uint32_t*)&Ch[((((size_t)(b_ * NHEAD + h_)) * S_LEN + s_) << 6) + d_] = packh2(v0, v1);
                } else if (mode == 1) {
                    size_t o = (size_t)m * N + n;
                    *(float2*)&Cf[o] = make_float2(v0, v1);
                    *(uint32_t*)&Ch[o] = packh2(v0, v1);
                } else if (mode == 2) {
                    v0 = fmaxf(v0, 0.f); v1 = fmaxf(v1, 0.f);
                    *(uint32_t*)&Ch[(size_t)m * N + n] = packh2(v0, v1);
                } else {
                    size_t o = (size_t)m * N + n;
                    float2 r = *(const float2*)&Res[o];
                    *(float2*)&Cf[o] = make_float2(v0 + r.x, v1 + r.y);
                }
            }
        }
    }
}

__global__ __launch_bounds__(256, 2) void gemm_f(
    const __half* __restrict__ A, const __half* __restrict__ W,
    const float* __restrict__ bias, float* __restrict__ Cf, __half* __restrict__ Ch,
    const float* __restrict__ Res, int N, int K, int mode)
{
    gemm_body(A, W, bias, Cf, Ch, Res, N, K, mode);
}

__global__ __launch_bounds__(256, 2) void gemm_f_qkv(
    const float* __restrict__ b0, const float* __restrict__ b1, const float* __restrict__ b2,
    __half* __restrict__ c0, __half* __restrict__ c1, __half* __restrict__ c2)
{
    int z = blockIdx.z;
    const __half* A = (z == 0) ? &g_w16[O_SQ] : ((z == 1) ? &g_w16[O_SK] : &g_w16[O_SV]);
    const __half* W = (z == 0) ? &g_w16[O_WQ] : ((z == 1) ? &g_w16[O_WK] : &g_w16[O_WV]);
    const float* B = (z == 0) ? b0 : ((z == 1) ? b1 : b2);
    __half* C = (z == 0) ? c0 : ((z == 1) ? c1 : c2);
    gemm_body(A, W, B, nullptr, C, nullptr, HID, HID, (z == 0) ? 4 : 0);
}

// ---------------- flash attention: 3-stage K/V pipeline, gmem mask, l-via-MMA ---
// V cols 64-71 (unused padding in the 72-half stride) carry a ones column:
// col64 = 1.0 so one extra n=8 MMA per kc accumulates l in fp32 on the tensor pipe.
// cp.async only writes cols 0-63, so the ones persist across all tiles per stage.
// smem: Q 18432 | 3 x {K 9216, V 9216} = 73728 B (2 CTAs/SM)
#define AT_LDH 72
#define AT_STG 18432
#define OFF_KV 18432
#define ATTN_SMEM6 73728

__global__ __launch_bounds__(256, 2)
void attn_reg(const __half* __restrict__ Qg, const __half* __restrict__ Kg,
              const __half* __restrict__ Vg, const __half* __restrict__ Mh,
              __half* __restrict__ ctxh)
{
    extern __shared__ __align__(256) char smb[];
    __half* Qs = (__half*)smb;
    const uint32_t sb = smem_u32(smb);

    const int tid = threadIdx.x;
    const int lane = tid & 31;
    const int wr = tid >> 5;
    const int gID = lane >> 2;
    const int tg = lane & 3;
    const int bh = blockIdx.y;
    const int b = bh >> 4;
    const int h = bh & 15;
    const int q0 = blockIdx.x * 128;

    const __half* Kb = Kg + (size_t)bh * S_LEN * HDIM;
    const __half* Vb = Vg + (size_t)bh * S_LEN * HDIM;
    const __half* Mr1 = Mh + (size_t)b * S_LEN * S_LEN + (size_t)(q0 + wr * 16 + gID) * S_LEN + tg * 16;
    const __half* Mr2 = Mr1 + 8 * S_LEN;

    // stage Q
    const __half* Qp = Qg + ((size_t)bh * S_LEN + q0) * HDIM;
#pragma unroll
    for (int i = 0; i < 4; i++) {
        int idx = i * 256 + tid, r = idx >> 3, sg = idx & 7;
        *(uint4*)&Qs[r * AT_LDH + sg * 8] = *(const uint4*)(Qp + r * 64 + sg * 8);
    }

    // V ones-column init: 3 stages x 64 rows, cols 64-71 = {1,0,0,0,0,0,0,0}
    if (tid < 192) {
        int st = tid >> 6, r = tid & 63;
        uint4 u = make_uint4(0x00003C00u, 0u, 0u, 0u);
        *(uint4*)(smb + OFF_KV + st * AT_STG + 9216 + r * 144 + 128) = u;
    }

    // prologue: issue K/V tiles 0 and 1
#pragma unroll
    for (int pt = 0; pt < 2; pt++) {
        uint32_t dstb = sb + OFF_KV + pt * AT_STG;
        const __half* Kp = Kb + (size_t)pt * 64 * HDIM;
        const __half* Vp = Vb + (size_t)pt * 64 * HDIM;
#pragma unroll
        for (int i = 0; i < 2; i++) {
            int idx = i * 256 + tid, r = idx >> 3, sg = idx & 7;
            cp16(dstb + r * 144 + sg * 16, Kp + (size_t)r * 64 + sg * 8);
            cp16(dstb + 9216 + r * 144 + sg * 16, Vp + (size_t)r * 64 + sg * 8);
        }
        asm volatile("cp.async.commit_group;" ::: "memory");
    }
    __syncthreads();

    // Q fragments
    const int lt = lane >> 3, lr = lane & 7;
    uint32_t aQ[4][4];
#pragma unroll
    for (int kc = 0; kc < 4; kc++) {
        uint32_t ad = sb + (uint32_t)((wr * 16 + (lt & 1) * 8 + lr) * AT_LDH + kc * 16 + (lt >> 1) * 8) * 2;
        ldsm4(aQ[kc], ad);
    }

    float o[8][4];
#pragma unroll
    for (int j = 0; j < 8; j++)
#pragma unroll
        for (int e = 0; e < 4; e++) o[j][e] = 0.f;
    float ol[4] = {0.f, 0.f, 0.f, 0.f};    // l accumulator (col 64 of augmented V)

    const uint32_t kOffLane = (uint32_t)(((lt >> 1) * 8 + lr) * 144 + (lt & 1) * 16);
    const uint32_t vOffLane = (uint32_t)(((lt & 1) * 8 + lr) * 144 + (lt >> 1) * 16);
    const uint32_t lOffLane = (uint32_t)((lane & 15) * 144 + 128);   // ones-column ldsm.x2 rows
    const int nt = S_LEN / 64;

    for (int kt = 0; kt < nt; kt++) {
        if (kt + 1 < nt) cp_wait<1>();
        else cp_wait<0>();
        __syncthreads();

        // issue K/V for tile kt+2
        if (kt + 2 < nt) {
            uint32_t dstb = sb + OFF_KV + ((kt + 2) % 3) * AT_STG;
            const __half* Kp = Kb + (size_t)(kt + 2) * 64 * HDIM;
            const __half* Vp = Vb + (size_t)(kt + 2) * 64 * HDIM;
#pragma unroll
            for (int i = 0; i < 2; i++) {
                int idx = i * 256 + tid, r = idx >> 3, sg = idx & 7;
                cp16(dstb + r * 144 + sg * 16, Kp + (size_t)r * 64 + sg * 8);
                cp16(dstb + 9216 + r * 144 + sg * 16, Vp + (size_t)r * 64 + sg * 8);
            }
            asm volatile("cp.async.commit_group;" ::: "memory");
        }

        // early mask loads (latency hidden by QK MMAs below)
        uint4 m1a = *(const uint4*)(Mr1 + (size_t)kt * 64);
        uint4 m1b = *(const uint4*)(Mr1 + (size_t)kt * 64 + 8);
        uint4 m2a = *(const uint4*)(Mr2 + (size_t)kt * 64);
        uint4 m2b = *(const uint4*)(Mr2 + (size_t)kt * 64 + 8);

        const uint32_t stb = sb + OFF_KV + (kt % 3) * AT_STG;

        // T = Q @ K^T (T = scores*log2e via Q prescale)
        float c[8][4];
#pragma unroll
        for (int j = 0; j < 8; j++)
#pragma unroll
            for (int e = 0; e < 4; e++) c[j][e] = 0.f;
#pragma unroll
        for (int kc = 0; kc < 4; kc++) {
#pragma unroll
            for (int p = 0; p < 4; p++) {
                uint32_t bk4[4];
                ldsm4(bk4, stb + kOffLane + (uint32_t)(p * 16 * 144 + kc * 32));
                mma16816(c[2 * p],     aQ[kc], bk4);
                mma16816(c[2 * p + 1], aQ[kc], bk4 + 2);
            }
        }

        uint32_t mm1[8] = {m1a.x, m1a.y, m1a.z, m1a.w, m1b.x, m1b.y, m1b.z, m1b.w};
        uint32_t mm2[8] = {m2a.x, m2a.y, m2a.z, m2a.w, m2b.x, m2b.y, m2b.z, m2b.w};

        uint32_t aP[4][4];
#pragma unroll
        for (int j = 0; j < 8; j++) {
            __half2 t01 = __floats2half2_rn(c[j][0], c[j][1]);
            __half2 t23 = __floats2half2_rn(c[j][2], c[j][3]);
            t01 = __hadd2(t01, *(__half2*)&mm1[j]);
            t23 = __hadd2(t23, *(__half2*)&mm2[j]);
            int kc = j >> 1, sl = (j & 1) * 2;
            aP[kc][sl]     = hexp2(t01);
            aP[kc][sl + 1] = hexp2(t23);
        }

        // O += P @ V ;  l += P @ ones (col 64)
#pragma unroll
        for (int kc = 0; kc < 4; kc++) {
#pragma unroll
            for (int p = 0; p < 4; p++) {
                uint32_t bv[4];
                ldsm4t(bv, stb + 9216 + vOffLane + (uint32_t)(kc * 16 * 144 + p * 32));
                mma16816(o[2 * p],     aP[kc], bv);
                mma16816(o[2 * p + 1], aP[kc], bv + 2);
            }
            uint32_t bl[2];
            ldsm2t(bl, stb + 9216 + lOffLane + (uint32_t)(kc * 16 * 144));
            mma16816(ol, aP[kc], bl);
        }
    }

    // epilogue: l lives in tg=0 lanes (col 64); broadcast within each quad
    float l1 = __shfl_sync(0xffffffffu, ol[0], lane & ~3);
    float l2 = __shfl_sync(0xffffffffu, ol[2], lane & ~3);
    float inv1 = 1.f / l1, inv2 = 1.f / l2;
    __half* d1 = ctxh + ((size_t)b * S_LEN + q0 + wr * 16 + gID) * HID + h * 64;
    __half* d2 = d1 + 8 * HID;
#pragma unroll
    for (int j = 0; j < 8; j++) {
        *(uint32_t*)&d1[j * 8 + tg * 2] = packh2(o[j][0] * inv1, o[j][1] * inv1);
        *(uint32_t*)&d2[j * 8 + tg * 2] = packh2(o[j][2] * inv2, o[j][3] * inv2);
    }
}

// ---------------- launch ----------------
extern "C" void kernel_launch(void* const* d_in, const int* in_sizes, int n_in,
                              void* d_out, int out_size)
{
    const float* srcQ = (const float*)d_in[0];
    const float* srcK = (const float*)d_in[1];
    const float* srcV = (const float*)d_in[2];
    const void*  mask = d_in[3];
    const float* wq = (const float*)d_in[4];
    const float* bq = (const float*)d_in[5];
    const float* wk = (const float*)d_in[6];
    const float* bk = (const float*)d_in[7];
    const float* wv = (const float*)d_in[8];
    const float* bv = (const float*)d_in[9];
    const float* wo = (const float*)d_in[10];
    const float* bo = (const float*)d_in[11];
    const float* w1 = (const float*)d_in[12];
    const float* b1 = (const float*)d_in[13];
    const float* w2 = (const float*)d_in[14];
    const float* b2 = (const float*)d_in[15];
    float* out = (float*)d_out;

    __half *Qp, *Kp, *Vp, *Ctxh, *Atth, *Ffnh, *W16, *Mhp;
    float *Att;
    cudaGetSymbolAddress((void**)&Qp, g_Qh);
    cudaGetSymbolAddress((void**)&Kp, g_Kh);
    cudaGetSymbolAddress((void**)&Vp, g_Vh);
    cudaGetSymbolAddress((void**)&Ctxh, g_ctxh);
    cudaGetSymbolAddress((void**)&Att, g_att);
    cudaGetSymbolAddress((void**)&Atth, g_atth);
    cudaGetSymbolAddress((void**)&Ffnh, g_ffnh);
    cudaGetSymbolAddress((void**)&W16, g_w16);
    cudaGetSymbolAddress((void**)&Mhp, g_maskh);

    static cudaStream_t s1 = nullptr;
    static cudaEvent_t ev0 = nullptr, ev1 = nullptr;
    if (s1 == nullptr) {
        cudaStreamCreateWithFlags(&s1, cudaStreamNonBlocking);
        cudaEventCreateWithFlags(&ev0, cudaEventDisableTiming);
        cudaEventCreateWithFlags(&ev1, cudaEventDisableTiming);
    }

    cudaFuncSetAttribute(gemm_f, cudaFuncAttributeMaxDynamicSharedMemorySize, GEMM_SMEM3);
    cudaFuncSetAttribute(gemm_f_qkv, cudaFuncAttributeMaxDynamicSharedMemorySize, GEMM_SMEM3);
    cudaFuncSetAttribute(attn_reg, cudaFuncAttributeMaxDynamicSharedMemorySize, ATTN_SMEM6);

    // fork: side stream does mask prep + wo/w1/w2 conversion
    cudaEventRecord(ev0, 0);
    cudaStreamWaitEvent(s1, ev0, 0);
    detect_mask_kernel<<<1, 1024, 0, s1>>>((const unsigned int*)mask);
    mask_convert_h<<<(int)((size_t)BATCH * S_LEN * S_LEN / 2048), 256, 0, s1>>>(mask);
    f2h_all<<<4608, 256, 0, s1>>>(srcQ, srcK, srcV, wq, wk, wv, wo, w1, w2, 7680);

    // main stream: srcs + QKV weights, then QKV projections
    f2h_all<<<7680, 256>>>(srcQ, srcK, srcV, wq, wk, wv, wo, w1, w2, 0);
    gemm_f_qkv<<<dim3(HID / 128, MTOT / 128, 3), 256, GEMM_SMEM3>>>(bq, bk, bv, Qp, Kp, Vp);

    // join: attention needs mask; O-proj needs wo
    cudaEventRecord(ev1, s1);
    cudaStreamWaitEvent(0, ev1, 0);

    attn_reg<<<dim3(S_LEN / 128, BATCH * NHEAD), 256, ATTN_SMEM6>>>(Qp, Kp, Vp, Mhp, Ctxh);

    gemm_f<<<dim3(HID / 128, MTOT / 128), 256, GEMM_SMEM3>>>(
        Ctxh, &W16[O_WO], bo, Att, Atth, nullptr, HID, HID, 1);
    gemm_f<<<dim3(FFN_D / 128, MTOT / 128), 256, GEMM_SMEM3>>>(
        Atth, &W16[O_W1], b1, nullptr, Ffnh, nullptr, FFN_D, HID, 2);
    gemm_f<<<dim3(HID / 128, MTOT / 128), 256, GEMM_SMEM3>>>(
        Ffnh, &W16[O_W2], b2, out, nullptr, Att, HID, FFN_D, 3);
}